// round 9
// baseline (speedup 1.0000x reference)
#include <cuda_runtime.h>
#include <cstdint>
#include <cstddef>

// ---------------------------------------------------------------------------
// Bidirectional LSTM. 512 seqs (256 batch x 2 dirs), 4 per CTA, 128 CTAs.
//
// Round 9: simple 2-barrier lockstep, fused gates, x-path in epilogue shadow.
//   Gate threads (warps 8-15): thread = 2 rows x (32h + 16enc) k-half.
//     Phase A: acc += Wh.h(t)  (128 FFMA2) -> STS partials.
//     Phase B: acc  = bias + Wih.enc(t+1)  (64 FFMA2, h-independent).
//   Service threads (warps 0-7): Phase A: stage1 enc(t+2) + x loader.
//     Phase B: epilogue, 1 cell/thread.
//   Two __syncthreads per step; no named barriers.
// ---------------------------------------------------------------------------

#define T_STEPS 4096
#define HID     64
#define KIN     60
#define ENC     32

__device__ float g_cfin[2][256][HID];

typedef unsigned long long ull;

__device__ __forceinline__ ull pack2(float lo, float hi) {
    ull u;
    asm("mov.b64 %0, {%1, %2};" : "=l"(u) : "f"(lo), "f"(hi));
    return u;
}
__device__ __forceinline__ void unpack2(ull u, float& lo, float& hi) {
    asm("mov.b64 {%0, %1}, %2;" : "=f"(lo), "=f"(hi) : "l"(u));
}
__device__ __forceinline__ void ffma2(ull& d, ull a, ull b) {
    asm("fma.rn.f32x2 %0, %1, %2, %0;" : "+l"(d) : "l"(a), "l"(b));
}
__device__ __forceinline__ float fast_sigmoid(float x) {
    return __fdividef(1.0f, 1.0f + __expf(-x));
}
__device__ __forceinline__ float fast_tanh(float x) {
    return 1.0f - __fdividef(2.0f, __expf(2.0f * x) + 1.0f);
}

__global__ void pad_kernel() {}

// ---------------------------------------------------------------------------
__global__ void __launch_bounds__(512, 1)
lstm_kernel(const float* __restrict__ cin,
            const float* __restrict__ W_enc,  const float* __restrict__ b_enc,
            const float* __restrict__ W_ih_f, const float* __restrict__ W_hh_f,
            const float* __restrict__ b_f,
            const float* __restrict__ W_ih_b, const float* __restrict__ W_hh_b,
            const float* __restrict__ b_b) {
    const int dir = blockIdx.x >> 6;
    const int bg  = blockIdx.x & 63;
    const int tid = threadIdx.x;

    __shared__ __align__(16) float  hbuf[4][HID];      // h_t per seq
    __shared__ __align__(16) float  xr[4][3][KIN];     // raw x ring per seq
    __shared__ __align__(16) float  encr[4][3][ENC];   // encoded x ring per seq
    __shared__ __align__(8)  float  gps[4][2][256];    // gate partials [seq][kh]
    __shared__ __align__(8)  float2 wesmT[30][ENC];    // W_enc transposed pairs

    const float* W_ih = dir ? W_ih_b : W_ih_f;
    const float* W_hh = dir ? W_hh_b : W_hh_f;
    const float* bv   = dir ? b_b    : b_f;

#define TMAP(t) (dir ? (T_STEPS - 1 - (t)) : (t))

    // wesmT fill (all threads): wesmT[i][r] = (W_enc[r][2i], W_enc[r][2i+1])
    for (int idx = tid; idx < 30 * ENC; idx += 512) {
        const int i = idx >> 5, r = idx & 31;
        wesmT[i][r] = make_float2(W_enc[r * KIN + 2 * i], W_enc[r * KIN + 2 * i + 1]);
    }

    if (tid >= 256) {
        // ================= gate threads: warps 8-15 =================
        const int p  = tid - 256;
        const int kh = p >> 7;          // k-half: h dims [32kh,32kh+32), enc [16kh,16kh+16)
        const int pr = p & 127;
        const int r0 = 2 * pr;          // 2 gate rows

        ull whA[16], whB[16], wiA[8], wiB[8];
        {
            const float* a = W_hh + (size_t)r0 * HID + kh * 32;
            const float* b = a + HID;
#pragma unroll
            for (int i = 0; i < 16; i++) {
                float2 x = *reinterpret_cast<const float2*>(a + 2 * i);
                float2 y = *reinterpret_cast<const float2*>(b + 2 * i);
                whA[i] = pack2(x.x, x.y);
                whB[i] = pack2(y.x, y.y);
            }
            const float* c2 = W_ih + (size_t)r0 * ENC + kh * 16;
            const float* d2 = c2 + ENC;
#pragma unroll
            for (int i = 0; i < 8; i++) {
                float2 x = *reinterpret_cast<const float2*>(c2 + 2 * i);
                float2 y = *reinterpret_cast<const float2*>(d2 + 2 * i);
                wiA[i] = pack2(x.x, x.y);
                wiB[i] = pack2(y.x, y.y);
            }
        }
        const ull biasA = (kh == 0) ? pack2(bv[r0], 0.0f)     : 0ull;
        const ull biasB = (kh == 0) ? pack2(bv[r0 + 1], 0.0f) : 0ull;

        __syncthreads();   // #1: wesmT, xr(0..2), hbuf=0 visible
        __syncthreads();   // #2: enc(0), enc(1) visible

        // init acc = bias + Wih.enc(0)
        ull accA[4], accB[4];
#pragma unroll
        for (int s = 0; s < 4; s++) {
            ull aA = biasA, aB = biasB;
            const float* eb = &encr[s][0][kh * 16];
#pragma unroll
            for (int c = 0; c < 4; c++) {
                const ulonglong2 v = *reinterpret_cast<const ulonglong2*>(eb + 4 * c);
                ffma2(aA, wiA[2 * c], v.x); ffma2(aA, wiA[2 * c + 1], v.y);
                ffma2(aB, wiB[2 * c], v.x); ffma2(aB, wiB[2 * c + 1], v.y);
            }
            accA[s] = aA; accB[s] = aB;
        }

        int m3n = 1;                    // (t+1) % 3
        for (int t = 0; t < T_STEPS; t++) {
            // ---- phase A: acc += Wh . h(t); publish partials ----
#pragma unroll
            for (int s = 0; s < 4; s++) {
                ull aA = accA[s], aB = accB[s];
                const float* hb = &hbuf[s][kh * 32];
#pragma unroll
                for (int c = 0; c < 8; c++) {
                    const ulonglong2 v = *reinterpret_cast<const ulonglong2*>(hb + 4 * c);
                    ffma2(aA, whA[2 * c], v.x); ffma2(aA, whA[2 * c + 1], v.y);
                    ffma2(aB, whB[2 * c], v.x); ffma2(aB, whB[2 * c + 1], v.y);
                }
                float lA, hA, lB, hB;
                unpack2(aA, lA, hA);
                unpack2(aB, lB, hB);
                *reinterpret_cast<float2*>(&gps[s][kh][r0]) = make_float2(lA + hA, lB + hB);
            }
            __syncthreads();   // BAR A: partials(t) ready; hbuf reads retired

            // ---- phase B (epilogue shadow): acc = bias + Wih.enc(t+1) ----
            if (t + 1 < T_STEPS) {
#pragma unroll
                for (int s = 0; s < 4; s++) {
                    ull aA = biasA, aB = biasB;
                    const float* eb = &encr[s][m3n][kh * 16];
#pragma unroll
                    for (int c = 0; c < 4; c++) {
                        const ulonglong2 v = *reinterpret_cast<const ulonglong2*>(eb + 4 * c);
                        ffma2(aA, wiA[2 * c], v.x); ffma2(aA, wiA[2 * c + 1], v.y);
                        ffma2(aB, wiB[2 * c], v.x); ffma2(aB, wiB[2 * c + 1], v.y);
                    }
                    accA[s] = aA; accB[s] = aB;
                }
            }
            __syncthreads();   // BAR B: h(t+1) + enc reads retired
            m3n = (m3n == 2) ? 0 : m3n + 1;
        }
    } else {
        // ================= service threads: warps 0-7 =================
        const int s = tid >> 6;        // my sequence
        const int j = tid & 63;        // cell / enc row / loader elem

        const float* cb = cin + ((size_t)(bg * 4 + s) * T_STEPS) * KIN + j;
        float xa   = 0.0f;
        float benc = (j < ENC) ? b_enc[j] : 0.0f;

        hbuf[s][j] = 0.0f;             // h0 = 0
        if (j < KIN) {                 // x(0..2) into ring; LDG x(3)
            xr[s][0][j] = __ldg(cb + (size_t)TMAP(0) * KIN);
            xr[s][1][j] = __ldg(cb + (size_t)TMAP(1) * KIN);
            xr[s][2][j] = __ldg(cb + (size_t)TMAP(2) * KIN);
            xa          = __ldg(cb + (size_t)TMAP(3) * KIN);
        }
        __syncthreads();   // #1

        // prologue: enc(0), enc(1)
        if (j < ENC) {
#pragma unroll
            for (int m = 0; m < 2; m++) {
                ull acc = 0ull;
                const float* xb = &xr[s][m][0];
#pragma unroll
                for (int c = 0; c < 15; c++) {
                    const ulonglong2 v = *reinterpret_cast<const ulonglong2*>(xb + 4 * c);
                    ffma2(acc, *reinterpret_cast<const ull*>(&wesmT[2 * c][j]), v.x);
                    ffma2(acc, *reinterpret_cast<const ull*>(&wesmT[2 * c + 1][j]), v.y);
                }
                float l, h;
                unpack2(acc, l, h);
                encr[s][m][j] = benc + l + h;
            }
        }
        __syncthreads();   // #2

        float cst = 0.0f;
        int sl2 = 2;                   // (t+2) % 3
        int sl3 = 0;                   // (t+3) % 3
        for (int t = 0; t < T_STEPS; t++) {
            // ---- phase A: stage1 enc(t+2) + x loader ----
            if (j < ENC && (t + 2) < T_STEPS) {
                ull acc = 0ull;
                const float* xb = &xr[s][sl2][0];
#pragma unroll
                for (int c = 0; c < 15; c++) {
                    const ulonglong2 v = *reinterpret_cast<const ulonglong2*>(xb + 4 * c);
                    ffma2(acc, *reinterpret_cast<const ull*>(&wesmT[2 * c][j]), v.x);
                    ffma2(acc, *reinterpret_cast<const ull*>(&wesmT[2 * c + 1][j]), v.y);
                }
                float l, h;
                unpack2(acc, l, h);
                encr[s][sl2][j] = benc + l + h;
            }
            if (j < KIN) {
                if (t + 3 < T_STEPS) xr[s][sl3][j] = xa;
                if (t + 4 < T_STEPS) xa = __ldg(cb + (size_t)TMAP(t + 4) * KIN);
            }
            __syncthreads();   // BAR A: partials(t) ready

            // ---- phase B: epilogue, 1 cell ----
            {
                const float gi = gps[s][0][j]       + gps[s][1][j];
                const float gf = gps[s][0][64 + j]  + gps[s][1][64 + j];
                const float gg = gps[s][0][128 + j] + gps[s][1][128 + j];
                const float go = gps[s][0][192 + j] + gps[s][1][192 + j];

                const float ig = fast_sigmoid(gi);
                const float fg = fast_sigmoid(gf);
                const float og = fast_sigmoid(go);
                const float gt = fast_tanh(gg);
                cst = fg * cst + ig * gt;
                hbuf[s][j] = og * fast_tanh(cst);
            }
            __syncthreads();   // BAR B: h(t+1) published
            sl2 = (sl2 == 2) ? 0 : sl2 + 1;
            sl3 = (sl3 == 2) ? 0 : sl3 + 1;
        }
        g_cfin[dir][bg * 4 + s][j] = cst;
    }
}

// ---------------------------------------------------------------------------
__global__ void final_kernel(const float* __restrict__ W_fin,
                             const float* __restrict__ b_fin,
                             float* __restrict__ out) {
    const int b = threadIdx.x;
    float a0 = b_fin[0], a1 = b_fin[1], a2 = b_fin[2];
#pragma unroll
    for (int j = 0; j < HID; j++) {
        const float cf = g_cfin[0][b][j];
        a0 += W_fin[0 * 128 + j] * cf;
        a1 += W_fin[1 * 128 + j] * cf;
        a2 += W_fin[2 * 128 + j] * cf;
    }
#pragma unroll
    for (int j = 0; j < HID; j++) {
        const float cb = g_cfin[1][b][j];
        a0 += W_fin[0 * 128 + 64 + j] * cb;
        a1 += W_fin[1 * 128 + 64 + j] * cb;
        a2 += W_fin[2 * 128 + 64 + j] * cb;
    }
    out[b * 3 + 0] = a0;
    out[b * 3 + 1] = a1;
    out[b * 3 + 2] = a2;
}

extern "C" void kernel_launch(void* const* d_in, const int* in_sizes, int n_in,
                              void* d_out, int out_size) {
    (void)in_sizes; (void)n_in; (void)out_size;
    const float* c      = (const float*)d_in[0];
    const float* W_enc  = (const float*)d_in[1];
    const float* b_enc  = (const float*)d_in[2];
    const float* W_ih_f = (const float*)d_in[3];
    const float* W_hh_f = (const float*)d_in[4];
    const float* b_f    = (const float*)d_in[5];
    const float* W_ih_b = (const float*)d_in[6];
    const float* W_hh_b = (const float*)d_in[7];
    const float* b_b    = (const float*)d_in[8];
    const float* W_fin  = (const float*)d_in[9];
    const float* b_fin  = (const float*)d_in[10];
    float* out = (float*)d_out;

    // 3 pads keep ncu -s 5 -c 1 aligned on lstm_kernel
    pad_kernel<<<1, 32>>>();
    pad_kernel<<<1, 32>>>();
    pad_kernel<<<1, 32>>>();
    lstm_kernel<<<128, 512>>>(c, W_enc, b_enc,
                              W_ih_f, W_hh_f, b_f,
                              W_ih_b, W_hh_b, b_b);
    final_kernel<<<1, 256>>>(W_fin, b_fin, out);
}

// round 10
// speedup vs baseline: 1.8901x; 1.8901x over previous
#include <cuda_runtime.h>
#include <cstdint>
#include <cstddef>

// ---------------------------------------------------------------------------
// Bidirectional LSTM, restructured as:
//   1) prepass_kernel: gx[dir][b][n][gate] = b_lstm + W_ih.(W_enc.x + b_enc)
//      for ALL timesteps (massively parallel GEMM, no recurrence), staged in
//      two 1GB __device__ arrays. dir=1 stored in reversed-t order.
//   2) recur_kernel: h-recurrence only. 256 CTAs x 256 thr, 2 CTAs/SM,
//      2 seqs/CTA; thread = 2 gate rows x 32-h k-half (weights in regs);
//      gx streamed from GMEM with distance-2 register prefetch.
//   3) final_kernel: out = W_fin . concat(c_fwd, c_bwd) + b_fin.
// ---------------------------------------------------------------------------

#define T_STEPS 4096
#define HID     64
#define KIN     60
#define ENC     32

__device__ float g_gx0[256ULL * T_STEPS * 256];   // 1 GB, dir 0
__device__ float g_gx1[256ULL * T_STEPS * 256];   // 1 GB, dir 1 (reversed t)
__device__ float g_cfin[2][256][HID];

typedef unsigned long long ull;

__device__ __forceinline__ ull pack2(float lo, float hi) {
    ull u;
    asm("mov.b64 %0, {%1, %2};" : "=l"(u) : "f"(lo), "f"(hi));
    return u;
}
__device__ __forceinline__ void unpack2(ull u, float& lo, float& hi) {
    asm("mov.b64 {%0, %1}, %2;" : "=f"(lo), "=f"(hi) : "l"(u));
}
__device__ __forceinline__ void ffma2(ull& d, ull a, ull b) {
    asm("fma.rn.f32x2 %0, %1, %2, %0;" : "+l"(d) : "l"(a), "l"(b));
}
__device__ __forceinline__ float fast_sigmoid(float x) {
    return __fdividef(1.0f, 1.0f + __expf(-x));
}
__device__ __forceinline__ float fast_tanh(float x) {
    return 1.0f - __fdividef(2.0f, __expf(2.0f * x) + 1.0f);
}

__global__ void pad_kernel() {}

// ---------------------------------------------------------------------------
// Prepass: grid 2048 = (b: 256) x (chunk: 8 of 512 t), block 256.
//   dgroup = tid>>7 selects direction; lt = tid&127 -> 2 gate rows.
//   Per 64-t sub-tile: load c -> enc (warp = 8 t's, lane = enc row) -> gx.
// ---------------------------------------------------------------------------
__global__ void __launch_bounds__(256, 2)
prepass_kernel(const float* __restrict__ cin,
               const float* __restrict__ W_enc, const float* __restrict__ b_enc,
               const float* __restrict__ W_ih_f, const float* __restrict__ b_f,
               const float* __restrict__ W_ih_b, const float* __restrict__ b_b) {
    const int b     = blockIdx.x >> 3;
    const int chunk = blockIdx.x & 7;
    const int t0    = chunk * 512;
    const int tid   = threadIdx.x;
    const int dg    = tid >> 7;        // direction group
    const int lt    = tid & 127;
    const int r0    = 2 * lt;          // 2 gate rows

    __shared__ __align__(16) float  c_sm[64][KIN];    // 15360 B
    __shared__ __align__(16) float  enc_sm[64][ENC];  //  8192 B
    __shared__ __align__(8)  float2 wT[30][ENC];      //  7680 B

    const float* W_ih = dg ? W_ih_b : W_ih_f;
    const float* bv   = dg ? b_b    : b_f;
    float* gxbase     = dg ? g_gx1  : g_gx0;

    // W_ih rows r0, r0+1 into regs (16 pairs each)
    ull wi0[16], wi1[16];
#pragma unroll
    for (int i = 0; i < 16; i++) {
        float2 p = *reinterpret_cast<const float2*>(W_ih + (size_t)r0 * ENC + 2 * i);
        float2 q = *reinterpret_cast<const float2*>(W_ih + (size_t)(r0 + 1) * ENC + 2 * i);
        wi0[i] = pack2(p.x, p.y);
        wi1[i] = pack2(q.x, q.y);
    }
    const float bias0 = bv[r0];
    const float bias1 = bv[r0 + 1];

    // transposed encoder weights: wT[i][e] = (W_enc[e][2i], W_enc[e][2i+1])
    for (int idx = tid; idx < 30 * ENC; idx += 256) {
        const int i = idx >> 5, e = idx & 31;
        wT[i][e] = make_float2(W_enc[e * KIN + 2 * i], W_enc[e * KIN + 2 * i + 1]);
    }
    const float benc  = b_enc[tid & 31];
    const int   ewarp = tid >> 5;      // 8 warps x 8 t's
    const int   ej    = tid & 31;      // enc row

    for (int ss = 0; ss < 8; ss++) {
        const int tb = t0 + ss * 64;
        __syncthreads();   // prior gx reads of enc_sm done; wT ready (ss=0)

        // load c[b, tb:tb+64, :] (contiguous)
        {
            const float* src = cin + ((size_t)b * T_STEPS + tb) * KIN;
            for (int i = tid; i < 64 * KIN; i += 256)
                (&c_sm[0][0])[i] = src[i];
        }
        __syncthreads();

        // enc: warp ewarp handles t = ewarp*8 + tt, lane ej = enc row
#pragma unroll
        for (int tt = 0; tt < 8; tt++) {
            const int t = ewarp * 8 + tt;
            ull acc = 0ull;
            const float* crow = &c_sm[t][0];
#pragma unroll
            for (int i = 0; i < 15; i++) {
                const ulonglong2 v = *reinterpret_cast<const ulonglong2*>(crow + 4 * i);
                ffma2(acc, *reinterpret_cast<const ull*>(&wT[2 * i][ej]), v.x);
                ffma2(acc, *reinterpret_cast<const ull*>(&wT[2 * i + 1][ej]), v.y);
            }
            float l, h;
            unpack2(acc, l, h);
            enc_sm[t][ej] = benc + l + h;
        }
        __syncthreads();

        // gx: every thread, 2 rows x all 64 t
        for (int tt = 0; tt < 64; tt++) {
            ull a0 = pack2(bias0, 0.0f);
            ull a1 = pack2(bias1, 0.0f);
            const float* erow = &enc_sm[tt][0];
#pragma unroll
            for (int c = 0; c < 8; c++) {
                const ulonglong2 v = *reinterpret_cast<const ulonglong2*>(erow + 4 * c);
                ffma2(a0, wi0[2 * c], v.x); ffma2(a0, wi0[2 * c + 1], v.y);
                ffma2(a1, wi1[2 * c], v.x); ffma2(a1, wi1[2 * c + 1], v.y);
            }
            const int t = tb + tt;
            const int n = dg ? (T_STEPS - 1 - t) : t;
            float l0, h0, l1, h1;
            unpack2(a0, l0, h0);
            unpack2(a1, l1, h1);
            *reinterpret_cast<float2*>(gxbase + ((size_t)b * T_STEPS + n) * 256 + r0) =
                make_float2(l0 + h0, l1 + h1);
        }
    }
}

// ---------------------------------------------------------------------------
// Recurrent: grid 256 = (dir: 2) x (bg: 128 pairs), block 256, 2 CTAs/SM.
//   kh = tid>>7 k-half; rh = tid&127 -> 2 gate rows. 2 seqs per CTA.
// ---------------------------------------------------------------------------
__global__ void __launch_bounds__(256, 2)
recur_kernel(const float* __restrict__ W_hh_f,
             const float* __restrict__ W_hh_b) {
    const int dir = blockIdx.x >> 7;
    const int bg  = blockIdx.x & 127;
    const int tid = threadIdx.x;
    const int kh  = tid >> 7;
    const int rh  = tid & 127;
    const int r0  = 2 * rh;

    __shared__ __align__(16) float hbuf[2][HID];     // h_t per seq
    __shared__ __align__(8)  float gps[2][2][256];   // partials [seq][kh][gate]

    const float* W_hh = dir ? W_hh_b : W_hh_f;

    // Wh rows r0, r0+1, k-range [kh*32, kh*32+32)
    ull wh0[16], wh1[16];
#pragma unroll
    for (int i = 0; i < 16; i++) {
        float2 p = *reinterpret_cast<const float2*>(W_hh + (size_t)r0 * HID + kh * 32 + 2 * i);
        float2 q = *reinterpret_cast<const float2*>(W_hh + (size_t)(r0 + 1) * HID + kh * 32 + 2 * i);
        wh0[i] = pack2(p.x, p.y);
        wh1[i] = pack2(q.x, q.y);
    }

    const float* gxb = dir ? g_gx1 : g_gx0;
    const float* gp0 = gxb + ((size_t)(bg * 2 + 0) * T_STEPS) * 256 + r0;
    const float* gp1 = gxb + ((size_t)(bg * 2 + 1) * T_STEPS) * 256 + r0;

    // gx double-buffer regs: A = even t, B = odd t (distance-2 prefetch)
    float2 gA0, gA1, gB0, gB1;
    gA0 = gA1 = gB0 = gB1 = make_float2(0.0f, 0.0f);
    if (kh == 0) {
        gA0 = *reinterpret_cast<const float2*>(gp0);
        gA1 = *reinterpret_cast<const float2*>(gp1);
        gB0 = *reinterpret_cast<const float2*>(gp0 + 256);
        gB1 = *reinterpret_cast<const float2*>(gp1 + 256);
    }

    const int s_ep = (tid >> 6) & 1;
    const int j_ep = tid & 63;
    float cst = 0.0f;
    if (tid < 128) hbuf[s_ep][j_ep] = 0.0f;
    __syncthreads();

#define STEP_BODY(TT, G0, G1)                                                  \
    {                                                                          \
        ull a0A = (kh == 0) ? pack2(G0.x, 0.0f) : 0ull;                        \
        ull a0B = (kh == 0) ? pack2(G0.y, 0.0f) : 0ull;                        \
        ull a1A = (kh == 0) ? pack2(G1.x, 0.0f) : 0ull;                        \
        ull a1B = (kh == 0) ? pack2(G1.y, 0.0f) : 0ull;                        \
        if (kh == 0 && (TT) + 2 < T_STEPS) {                                   \
            G0 = *reinterpret_cast<const float2*>(gp0 + (size_t)((TT) + 2) * 256); \
            G1 = *reinterpret_cast<const float2*>(gp1 + (size_t)((TT) + 2) * 256); \
        }                                                                      \
        const float* hb0 = &hbuf[0][kh * 32];                                  \
        const float* hb1 = &hbuf[1][kh * 32];                                  \
        _Pragma("unroll")                                                      \
        for (int c = 0; c < 8; c++) {                                          \
            const ulonglong2 v0 = *reinterpret_cast<const ulonglong2*>(hb0 + 4 * c); \
            const ulonglong2 v1 = *reinterpret_cast<const ulonglong2*>(hb1 + 4 * c); \
            ffma2(a0A, wh0[2 * c], v0.x); ffma2(a0A, wh0[2 * c + 1], v0.y);    \
            ffma2(a0B, wh1[2 * c], v0.x); ffma2(a0B, wh1[2 * c + 1], v0.y);    \
            ffma2(a1A, wh0[2 * c], v1.x); ffma2(a1A, wh0[2 * c + 1], v1.y);    \
            ffma2(a1B, wh1[2 * c], v1.x); ffma2(a1B, wh1[2 * c + 1], v1.y);    \
        }                                                                      \
        float l0, h0, l1, h1;                                                  \
        unpack2(a0A, l0, h0); unpack2(a0B, l1, h1);                            \
        *reinterpret_cast<float2*>(&gps[0][kh][r0]) = make_float2(l0 + h0, l1 + h1); \
        unpack2(a1A, l0, h0); unpack2(a1B, l1, h1);                            \
        *reinterpret_cast<float2*>(&gps[1][kh][r0]) = make_float2(l0 + h0, l1 + h1); \
        __syncthreads();                                                       \
        if (tid < 128) {                                                       \
            const float gi = gps[s_ep][0][j_ep]       + gps[s_ep][1][j_ep];    \
            const float gf = gps[s_ep][0][64 + j_ep]  + gps[s_ep][1][64 + j_ep];  \
            const float gg = gps[s_ep][0][128 + j_ep] + gps[s_ep][1][128 + j_ep]; \
            const float go = gps[s_ep][0][192 + j_ep] + gps[s_ep][1][192 + j_ep]; \
            const float ig = fast_sigmoid(gi);                                 \
            const float fg = fast_sigmoid(gf);                                 \
            const float og = fast_sigmoid(go);                                 \
            const float gt = fast_tanh(gg);                                    \
            cst = fg * cst + ig * gt;                                          \
            hbuf[s_ep][j_ep] = og * fast_tanh(cst);                            \
        }                                                                      \
        __syncthreads();                                                       \
    }

    for (int t = 0; t < T_STEPS; t += 2) {
        STEP_BODY(t, gA0, gA1);
        STEP_BODY(t + 1, gB0, gB1);
    }
#undef STEP_BODY

    if (tid < 128) g_cfin[dir][bg * 2 + s_ep][j_ep] = cst;
}

// ---------------------------------------------------------------------------
__global__ void final_kernel(const float* __restrict__ W_fin,
                             const float* __restrict__ b_fin,
                             float* __restrict__ out) {
    const int b = threadIdx.x;
    float a0 = b_fin[0], a1 = b_fin[1], a2 = b_fin[2];
#pragma unroll
    for (int j = 0; j < HID; j++) {
        const float cf = g_cfin[0][b][j];
        a0 += W_fin[0 * 128 + j] * cf;
        a1 += W_fin[1 * 128 + j] * cf;
        a2 += W_fin[2 * 128 + j] * cf;
    }
#pragma unroll
    for (int j = 0; j < HID; j++) {
        const float cb = g_cfin[1][b][j];
        a0 += W_fin[0 * 128 + 64 + j] * cb;
        a1 += W_fin[1 * 128 + 64 + j] * cb;
        a2 += W_fin[2 * 128 + 64 + j] * cb;
    }
    out[b * 3 + 0] = a0;
    out[b * 3 + 1] = a1;
    out[b * 3 + 2] = a2;
}

extern "C" void kernel_launch(void* const* d_in, const int* in_sizes, int n_in,
                              void* d_out, int out_size) {
    (void)in_sizes; (void)n_in; (void)out_size;
    const float* c      = (const float*)d_in[0];
    const float* W_enc  = (const float*)d_in[1];
    const float* b_enc  = (const float*)d_in[2];
    const float* W_ih_f = (const float*)d_in[3];
    const float* W_hh_f = (const float*)d_in[4];
    const float* b_f    = (const float*)d_in[5];
    const float* W_ih_b = (const float*)d_in[6];
    const float* W_hh_b = (const float*)d_in[7];
    const float* b_b    = (const float*)d_in[8];
    const float* W_fin  = (const float*)d_in[9];
    const float* b_fin  = (const float*)d_in[10];
    float* out = (float*)d_out;

    prepass_kernel<<<2048, 256>>>(c, W_enc, b_enc, W_ih_f, b_f, W_ih_b, b_b);
    // 2 pads: recur_kernel lands 4th per call (matches prior ncu alignment)
    pad_kernel<<<1, 32>>>();
    pad_kernel<<<1, 32>>>();
    recur_kernel<<<256, 256>>>(W_hh_f, W_hh_b);
    final_kernel<<<1, 256>>>(W_fin, b_fin, out);
}